// round 1
// baseline (speedup 1.0000x reference)
#include <cuda_runtime.h>
#include <cuda_bf16.h>

// Sizes
#define W_WORDS 4096
#define LCH 32
#define D 256
#define D2 512
#define D4 1024
#define KDIM 1536   // 3*512

// Scratch (__device__ globals — no allocation allowed)
__device__ __align__(128) float   g_Wt[3 * 256 * 256];     // char conv w transposed [k][i][d]
__device__ __align__(128) float   g_T[3 * 128 * 256];      // lookup tables [k][c][d]
__device__ __align__(128) float   g_B[KDIM * D2];          // sentence conv w as [p=k*512+i][o]
__device__ __align__(128) float   g_u[W_WORDS * D2];       // concat features [w][512]
__device__ __align__(128) unsigned g_rkeys[D2];            // int-keyed running max per column
__device__ __align__(128) float   g_h[D4];                 // hidden layer

// ---------------- transposes + init ----------------
__global__ void k_tr_wc(const float* __restrict__ wc) {
    // wc: [d_out=256][i=256][k=3]; out g_Wt[k][i][d]
    int b = blockIdx.x;            // 768 = 3*256
    int k = b / 256, i = b % 256;
    int d = threadIdx.x;           // 256
    g_Wt[k * 65536 + i * 256 + d] = wc[d * 768 + i * 3 + k];
}

__global__ void k_tr_ws(const float* __restrict__ ws) {
    // ws: [o=512][i=512][k=3]; out g_B[p=k*512+i][o]
    int p = blockIdx.x;            // 1536
    int k = p / 512, i = p % 512;
    int o = threadIdx.x;           // 512
    g_B[p * 512 + o] = ws[o * 1536 + i * 3 + k];
    if (p == 0) g_rkeys[o] = 0u;   // reset running max each launch (deterministic)
}

// ---------------- char tables: T_k[c][d] = sum_i chr_emb[c][i] * Wc[d][i][k] ----------------
__global__ void k_tables(const float* __restrict__ chr_emb) {
    __shared__ float ce[2][256];
    int d = threadIdx.x;
    int c0 = blockIdx.x * 2;       // 64 blocks -> 128 chars
    ce[0][d] = chr_emb[c0 * 256 + d];
    ce[1][d] = chr_emb[(c0 + 1) * 256 + d];
    __syncthreads();
    float a00 = 0.f, a01 = 0.f, a02 = 0.f, a10 = 0.f, a11 = 0.f, a12 = 0.f;
    #pragma unroll 8
    for (int i = 0; i < 256; i++) {
        float e0 = ce[0][i], e1 = ce[1][i];
        float w0 = g_Wt[i * 256 + d];
        float w1 = g_Wt[65536 + i * 256 + d];
        float w2 = g_Wt[131072 + i * 256 + d];
        a00 += e0 * w0; a01 += e0 * w1; a02 += e0 * w2;
        a10 += e1 * w0; a11 += e1 * w1; a12 += e1 * w2;
    }
    g_T[0 * 32768 + c0 * 256 + d] = a00;
    g_T[1 * 32768 + c0 * 256 + d] = a01;
    g_T[2 * 32768 + c0 * 256 + d] = a02;
    g_T[0 * 32768 + (c0 + 1) * 256 + d] = a10;
    g_T[1 * 32768 + (c0 + 1) * 256 + d] = a11;
    g_T[2 * 32768 + (c0 + 1) * 256 + d] = a12;
}

// ---------------- build u: word emb gather + char conv (table lookups) + maxpool ----------------
__global__ void k_build_u(const int* __restrict__ words,
                          const int* __restrict__ wic,
                          const float* __restrict__ word_emb,
                          const float* __restrict__ cb) {
    int w = blockIdx.x;            // 4096
    int d = threadIdx.x;           // 256
    __shared__ int codes[LCH];
    if (d < LCH) codes[d] = wic[w * LCH + d];
    __syncthreads();

    int wi = words[w];
    g_u[w * D2 + d] = word_emb[wi * 256 + d];

    const float* T0 = g_T;
    const float* T1 = g_T + 32768;
    const float* T2 = g_T + 65536;
    float bb = cb[d];

    // Rolling partials: out[t] = cb + T0[c_{t-1}] + T1[c_t] + T2[c_{t+1}]
    int c = codes[0];
    float a0 = T0[c * 256 + d], a1 = T1[c * 256 + d], a2 = T2[c * 256 + d];
    float accA = bb + a1;          // out[0] partial (waiting T2[c1])
    float accB = bb + a0;          // out[1] partial
    float m = -1e30f;
    (void)a2;
    #pragma unroll
    for (int t = 1; t < LCH; t++) {
        c = codes[t];
        a0 = T0[c * 256 + d]; a1 = T1[c * 256 + d]; a2 = T2[c * 256 + d];
        m = fmaxf(m, accA + a2);   // out[t-1] complete
        accA = accB + a1;
        accB = bb + a0;
    }
    m = fmaxf(m, accA);            // out[31] (right pad contributes 0)
    g_u[w * D2 + 256 + d] = m;
}

// ---------------- sentence conv as GEMM + fused column max ----------------
// Y[w][o] = sum_p B[p][o] * X[w][p], X[w][p=k*512+i] = u[w+k-1][i] (zero-padded)
// bias added later (commutes with max). Tile 128(M) x 64(N) x 16(K), 256 threads, 8x4 micro.
#define BM 128
#define BN 64
#define BK 16

__global__ void k_gemm_max() {
    __shared__ float As[BK][BM];   // A^T
    __shared__ float Bs[BK][BN];
    int tid = threadIdx.x;
    int bn0 = blockIdx.x * BN;     // 8 n-tiles
    int w0  = blockIdx.y * BM;     // 32 m-tiles
    int tx = tid & 15, ty = tid >> 4;

    float acc[8][4];
    #pragma unroll
    for (int r = 0; r < 8; r++)
        #pragma unroll
        for (int cc = 0; cc < 4; cc++) acc[r][cc] = 0.f;

    for (int pc = 0; pc < KDIM / BK; ++pc) {
        int p0 = pc * BK;
        int k = p0 >> 9;           // which conv tap (16-chunks never straddle 512)
        int i0 = p0 & 511;
        int roff = k - 1;
        // A tile: 128x16 = 512 float4, 2 per thread, store transposed
        #pragma unroll
        for (int q = 0; q < 2; q++) {
            int fidx = tid + q * 256;
            int m = fidx >> 2;
            int kk4 = (fidx & 3) * 4;
            int row = w0 + m + roff;
            float4 v = make_float4(0.f, 0.f, 0.f, 0.f);
            if ((unsigned)row < (unsigned)W_WORDS)
                v = *(const float4*)&g_u[row * D2 + i0 + kk4];
            As[kk4 + 0][m] = v.x; As[kk4 + 1][m] = v.y;
            As[kk4 + 2][m] = v.z; As[kk4 + 3][m] = v.w;
        }
        // B tile: 16x64 = 256 float4, 1 per thread
        {
            int kk = tid >> 4;
            int n4 = (tid & 15) * 4;
            *(float4*)&Bs[kk][n4] = *(const float4*)&g_B[(p0 + kk) * D2 + bn0 + n4];
        }
        __syncthreads();
        #pragma unroll
        for (int kk = 0; kk < BK; kk++) {
            float4 A0 = *(const float4*)&As[kk][ty * 8];
            float4 A1 = *(const float4*)&As[kk][ty * 8 + 4];
            float4 Bv = *(const float4*)&Bs[kk][tx * 4];
            float ar[8] = {A0.x, A0.y, A0.z, A0.w, A1.x, A1.y, A1.z, A1.w};
            float br[4] = {Bv.x, Bv.y, Bv.z, Bv.w};
            #pragma unroll
            for (int r = 0; r < 8; r++)
                #pragma unroll
                for (int cc = 0; cc < 4; cc++)
                    acc[r][cc] += ar[r] * br[cc];
        }
        __syncthreads();
    }

    // per-thread max over its 8 rows
    float tmax[4];
    #pragma unroll
    for (int cc = 0; cc < 4; cc++) {
        tmax[cc] = acc[0][cc];
        #pragma unroll
        for (int r = 1; r < 8; r++) tmax[cc] = fmaxf(tmax[cc], acc[r][cc]);
    }
    // cross-ty reduce via smem (reuse As; last __syncthreads already drained readers)
    float* red = &As[0][0];        // 16*64 floats
    #pragma unroll
    for (int cc = 0; cc < 4; cc++) red[ty * 64 + tx * 4 + cc] = tmax[cc];
    __syncthreads();
    if (tid < 64) {
        float m = red[tid];
        #pragma unroll
        for (int q = 1; q < 16; q++) m = fmaxf(m, red[q * 64 + tid]);
        unsigned u = __float_as_uint(m);
        unsigned key = (u & 0x80000000u) ? ~u : (u | 0x80000000u);  // order-preserving
        atomicMax(&g_rkeys[bn0 + tid], key);
    }
}

// ---------------- head: h = tanh(W1 @ (r+sb) + b1) ----------------
__global__ void k_h(const float* __restrict__ sb,
                    const float* __restrict__ w1,
                    const float* __restrict__ b1) {
    __shared__ float rs[D2];
    int tid = threadIdx.x;         // 256
    for (int j = tid; j < D2; j += 256) {
        unsigned key = g_rkeys[j];
        unsigned u = (key & 0x80000000u) ? (key & 0x7FFFFFFFu) : ~key;
        rs[j] = __uint_as_float(u) + sb[j];   // add sentence-conv bias after max
    }
    __syncthreads();
    int g = tid >> 4, s = tid & 15;
    int o = blockIdx.x * 16 + g;   // 64 blocks -> 1024 outputs
    float accv = 0.f;
    for (int j = s; j < D2; j += 16) accv += w1[o * D2 + j] * rs[j];
    #pragma unroll
    for (int off = 8; off; off >>= 1) accv += __shfl_down_sync(0xffffffffu, accv, off, 16);
    if (s == 0) g_h[o] = tanhf(accv + b1[o]);
}

// ---------------- out = W2 @ h + b2 ----------------
__global__ void k_out(const float* __restrict__ w2,
                      const float* __restrict__ b2,
                      float* __restrict__ out) {
    int j = threadIdx.x >> 5, lane = threadIdx.x & 31;   // 64 threads, 2 outputs
    float accv = 0.f;
    for (int l = lane; l < D4; l += 32) accv += g_h[l] * w2[j * D4 + l];
    #pragma unroll
    for (int off = 16; off; off >>= 1) accv += __shfl_down_sync(0xffffffffu, accv, off);
    if (lane == 0) out[j] = accv + b2[j];
}

extern "C" void kernel_launch(void* const* d_in, const int* in_sizes, int n_in,
                              void* d_out, int out_size) {
    const int*   words       = (const int*)d_in[0];
    const int*   wic         = (const int*)d_in[1];
    const float* word_emb    = (const float*)d_in[2];
    const float* chr_emb     = (const float*)d_in[3];
    const float* conv_chr_w  = (const float*)d_in[4];
    const float* conv_chr_b  = (const float*)d_in[5];
    const float* conv_sent_w = (const float*)d_in[6];
    const float* conv_sent_b = (const float*)d_in[7];
    const float* w1          = (const float*)d_in[8];
    const float* b1          = (const float*)d_in[9];
    const float* w2          = (const float*)d_in[10];
    const float* b2          = (const float*)d_in[11];
    float* out = (float*)d_out;

    k_tr_wc<<<768, 256>>>(conv_chr_w);
    k_tr_ws<<<1536, 512>>>(conv_sent_w);
    k_tables<<<64, 256>>>(chr_emb);
    k_build_u<<<W_WORDS, 256>>>(words, wic, word_emb, conv_chr_b);
    dim3 g3(D2 / BN, W_WORDS / BM);
    k_gemm_max<<<g3, 256>>>();
    k_h<<<64, 256>>>(conv_sent_b, w1, b1);
    k_out<<<1, 64>>>(w2, b2, out);
}

// round 3
// speedup vs baseline: 1.9239x; 1.9239x over previous
#include <cuda_runtime.h>
#include <cuda_bf16.h>
#include <cstdint>

// Sizes
#define W_WORDS 4096
#define LCH 32
#define D2 512
#define D4 1024
#define KDIM 1536   // 3*512

// GEMM tiling
#define GM 128
#define GN 128
#define GK 32
#define NK (KDIM / GK)            // 48
#define TILE_B (GM * GK * 2)      // 8192 bytes per array (bf16)
#define STAGE_B (4 * TILE_B)      // 32768 : Ah, Al, Bh, Bl
#define NSTAGE 3
#define SMEM_DYN (NSTAGE * STAGE_B)   // 98304

// ---------------- scratch (__device__ globals) ----------------
__device__ __align__(128) float   g_Wt[3 * 256 * 256];     // char conv w transposed [k][i][d]
__device__ __align__(128) float   g_T[3 * 128 * 256];      // lookup tables [k][c][d]
__device__ __align__(128) __nv_bfloat16 g_uh[(W_WORDS + 2) * D2];  // padded u hi
__device__ __align__(128) __nv_bfloat16 g_ul[(W_WORDS + 2) * D2];  // padded u lo
__device__ __align__(128) __nv_bfloat16 g_Bh[D2 * KDIM];   // B hi: [o][p] K-major
__device__ __align__(128) __nv_bfloat16 g_Bl[D2 * KDIM];   // B lo
__device__ __align__(128) unsigned g_rkeys[D2];
__device__ __align__(128) float   g_h[D4];

// ---------------- helpers ----------------
__device__ __forceinline__ uint32_t smem_u32(const void* p) {
    uint32_t a;
    asm("{ .reg .u64 t; cvta.to.shared.u64 t, %1; cvt.u32.u64 %0, t; }" : "=r"(a) : "l"(p));
    return a;
}
__device__ __forceinline__ void ldmx4(uint32_t* r, uint32_t addr) {
    asm volatile("ldmatrix.sync.aligned.m8n8.x4.shared.b16 {%0,%1,%2,%3}, [%4];"
                 : "=r"(r[0]), "=r"(r[1]), "=r"(r[2]), "=r"(r[3]) : "r"(addr));
}
__device__ __forceinline__ void mma_bf16(float* c, const uint32_t* a, uint32_t b0, uint32_t b1) {
    asm volatile("mma.sync.aligned.m16n8k16.row.col.f32.bf16.bf16.f32 "
                 "{%0,%1,%2,%3}, {%4,%5,%6,%7}, {%8,%9}, {%0,%1,%2,%3};"
                 : "+f"(c[0]), "+f"(c[1]), "+f"(c[2]), "+f"(c[3])
                 : "r"(a[0]), "r"(a[1]), "r"(a[2]), "r"(a[3]), "r"(b0), "r"(b1));
}
__device__ __forceinline__ void cp16(uint32_t dst, const void* src) {
    asm volatile("cp.async.cg.shared.global [%0], [%1], 16;" :: "r"(dst), "l"(src));
}
#define CP_COMMIT() asm volatile("cp.async.commit_group;" ::: "memory")
#define CP_WAIT1()  asm volatile("cp.async.wait_group 1;" ::: "memory")

// ---------------- prep kernels ----------------
__global__ void k_tr_wc(const float* __restrict__ wc) {
    int b = blockIdx.x;            // 768 = 3*256
    int k = b / 256, i = b % 256;
    int d = threadIdx.x;
    g_Wt[k * 65536 + i * 256 + d] = wc[d * 768 + i * 3 + k];
}

__global__ void k_prep_B(const float* __restrict__ ws) {
    int o = blockIdx.x;            // 512
    for (int p = threadIdx.x; p < KDIM; p += 256) {
        int kk = p >> 9, i = p & 511;
        float v = ws[o * KDIM + i * 3 + kk];
        __nv_bfloat16 h = __float2bfloat16(v);
        g_Bh[o * KDIM + p] = h;
        g_Bl[o * KDIM + p] = __float2bfloat16(v - __bfloat162float(h));
    }
    if (blockIdx.x == 0) { g_rkeys[threadIdx.x] = 0u; g_rkeys[threadIdx.x + 256] = 0u; }
}

__global__ void k_tables(const float* __restrict__ chr_emb) {
    __shared__ float ce[2][256];
    int d = threadIdx.x;
    int c0 = blockIdx.x * 2;
    ce[0][d] = chr_emb[c0 * 256 + d];
    ce[1][d] = chr_emb[(c0 + 1) * 256 + d];
    __syncthreads();
    float a00 = 0.f, a01 = 0.f, a02 = 0.f, a10 = 0.f, a11 = 0.f, a12 = 0.f;
    #pragma unroll 8
    for (int i = 0; i < 256; i++) {
        float e0 = ce[0][i], e1 = ce[1][i];
        float w0 = g_Wt[i * 256 + d];
        float w1 = g_Wt[65536 + i * 256 + d];
        float w2 = g_Wt[131072 + i * 256 + d];
        a00 += e0 * w0; a01 += e0 * w1; a02 += e0 * w2;
        a10 += e1 * w0; a11 += e1 * w1; a12 += e1 * w2;
    }
    g_T[c0 * 256 + d] = a00;
    g_T[32768 + c0 * 256 + d] = a01;
    g_T[65536 + c0 * 256 + d] = a02;
    g_T[(c0 + 1) * 256 + d] = a10;
    g_T[32768 + (c0 + 1) * 256 + d] = a11;
    g_T[65536 + (c0 + 1) * 256 + d] = a12;
}

// ---------------- build u (bf16 hi/lo, padded), float2-vectorized ----------------
__global__ void k_build_u(const int* __restrict__ words,
                          const int* __restrict__ wic,
                          const float* __restrict__ word_emb,
                          const float* __restrict__ cb) {
    int w = blockIdx.x;            // 4096
    int t = threadIdx.x;           // 128
    __shared__ int codes[LCH];
    if (t < LCH) codes[t] = wic[w * LCH + t];
    __syncthreads();

    const float2* WE = (const float2*)word_emb;
    float2 wv = WE[(size_t)words[w] * 128 + t];
    __nv_bfloat162* UH = (__nv_bfloat162*)g_uh;
    __nv_bfloat162* UL = (__nv_bfloat162*)g_ul;
    {
        __nv_bfloat16 hx = __float2bfloat16(wv.x), hy = __float2bfloat16(wv.y);
        UH[(w + 1) * 256 + t] = __nv_bfloat162(hx, hy);
        UL[(w + 1) * 256 + t] = __nv_bfloat162(
            __float2bfloat16(wv.x - __bfloat162float(hx)),
            __float2bfloat16(wv.y - __bfloat162float(hy)));
    }

    const float2* T0 = (const float2*)g_T;
    const float2* T1 = (const float2*)(g_T + 32768);
    const float2* T2 = (const float2*)(g_T + 65536);
    float2 bb = ((const float2*)cb)[t];

    int c = codes[0];
    float2 a0 = T0[c * 128 + t], a1 = T1[c * 128 + t], a2 = T2[c * 128 + t];
    float2 accA = make_float2(bb.x + a1.x, bb.y + a1.y);
    float2 accB = make_float2(bb.x + a0.x, bb.y + a0.y);
    float2 m = make_float2(-1e30f, -1e30f);
    (void)a2;
    #pragma unroll
    for (int s = 1; s < LCH; s++) {
        c = codes[s];
        a0 = T0[c * 128 + t]; a1 = T1[c * 128 + t]; a2 = T2[c * 128 + t];
        m.x = fmaxf(m.x, accA.x + a2.x);
        m.y = fmaxf(m.y, accA.y + a2.y);
        accA.x = accB.x + a1.x; accA.y = accB.y + a1.y;
        accB.x = bb.x + a0.x;   accB.y = bb.y + a0.y;
    }
    m.x = fmaxf(m.x, accA.x);
    m.y = fmaxf(m.y, accA.y);
    {
        __nv_bfloat16 hx = __float2bfloat16(m.x), hy = __float2bfloat16(m.y);
        UH[(w + 1) * 256 + 128 + t] = __nv_bfloat162(hx, hy);
        UL[(w + 1) * 256 + 128 + t] = __nv_bfloat162(
            __float2bfloat16(m.x - __bfloat162float(hx)),
            __float2bfloat16(m.y - __bfloat162float(hy)));
    }
    // zero padding rows 0 and W+1
    __nv_bfloat162 z; z.x = __float2bfloat16(0.f); z.y = z.x;
    if (w == 0) {
        UH[t] = z; UH[128 + t] = z;
        UL[t] = z; UL[128 + t] = z;
    }
    if (w == W_WORDS - 1) {
        size_t r = (size_t)(W_WORDS + 1) * 256;
        UH[r + t] = z; UH[r + 128 + t] = z;
        UL[r + t] = z; UL[r + 128 + t] = z;
    }
}

// ---------------- tensor-core GEMM (mma.sync bf16 3-product) + fused column max ----------------
// Y[w][o] = sum_p X[w][p]*Wm[o][p]; A[m][k] row-major from g_u*, B[n][k] K-major from g_B*.
__global__ __launch_bounds__(256, 1) void k_gemm_mma() {
    extern __shared__ __align__(128) char smem[];
    uint32_t sb = smem_u32(smem);
    int tid = threadIdx.x;
    int lane = tid & 31, wq = tid >> 5;
    int wm = wq & 3, wn = wq >> 2;       // 4 m-warps x 2 n-warps
    int n0 = blockIdx.x * GN;
    int w0 = blockIdx.y * GM;

    float acc[2][8][4];
    #pragma unroll
    for (int a = 0; a < 2; a++)
        #pragma unroll
        for (int f = 0; f < 8; f++)
            #pragma unroll
            for (int r = 0; r < 4; r++) acc[a][f][r] = 0.f;

    auto issue_stage = [&](int ck, int s) {
        int p0 = ck * GK;
        int kk = p0 >> 9, i0 = p0 & 511;
        uint32_t st = sb + s * STAGE_B;
        #pragma unroll
        for (int q = 0; q < 8; q++) {
            int idx = tid + q * 256;      // 0..2047
            int arr = idx >> 9;           // 0:Ah 1:Al 2:Bh 3:Bl
            int j = idx & 511;
            int r = j >> 2, c4 = j & 3;
            uint32_t dst = st + arr * TILE_B + r * 64 + ((c4 ^ ((r >> 1) & 3)) << 4);
            const __nv_bfloat16* src;
            if (arr == 0)      src = g_uh + (size_t)(w0 + kk + r) * D2 + i0 + c4 * 8;
            else if (arr == 1) src = g_ul + (size_t)(w0 + kk + r) * D2 + i0 + c4 * 8;
            else if (arr == 2) src = g_Bh + (size_t)(n0 + r) * KDIM + p0 + c4 * 8;
            else               src = g_Bl + (size_t)(n0 + r) * KDIM + p0 + c4 * 8;
            cp16(dst, src);
        }
        CP_COMMIT();
    };

    issue_stage(0, 0);
    issue_stage(1, 1);

    for (int ck = 0; ck < NK; ck++) {
        CP_WAIT1();
        __syncthreads();
        if (ck + 2 < NK) issue_stage(ck + 2, (ck + 2) % NSTAGE);
        else CP_COMMIT();              // keep group counting aligned

        uint32_t st = sb + (ck % NSTAGE) * STAGE_B;
        uint32_t aH = st, aL = st + TILE_B, bH = st + 2 * TILE_B, bL = st + 3 * TILE_B;
        #pragma unroll
        for (int ks = 0; ks < 2; ks++) {
            uint32_t ah[2][4], al[2][4];
            #pragma unroll
            for (int mf = 0; mf < 2; mf++) {
                int row = wm * 32 + mf * 16 + (lane & 7) + ((lane >> 3) & 1) * 8;
                int c = 2 * ks + (lane >> 4);
                uint32_t off = (uint32_t)(row * 64) + (uint32_t)((c ^ ((row >> 1) & 3)) << 4);
                ldmx4(ah[mf], aH + off);
                ldmx4(al[mf], aL + off);
            }
            #pragma unroll
            for (int bq = 0; bq < 4; bq++) {
                int row = wn * 64 + bq * 16 + (lane & 7) + ((lane >> 3) & 1) * 8;
                int c = 2 * ks + (lane >> 4);
                uint32_t off = (uint32_t)(row * 64) + (uint32_t)((c ^ ((row >> 1) & 3)) << 4);
                uint32_t bh[4], bl[4];
                ldmx4(bh, bH + off);
                ldmx4(bl, bL + off);
                #pragma unroll
                for (int mf = 0; mf < 2; mf++) {
                    mma_bf16(acc[mf][2 * bq],     ah[mf], bh[0], bh[2]);
                    mma_bf16(acc[mf][2 * bq + 1], ah[mf], bh[1], bh[3]);
                    mma_bf16(acc[mf][2 * bq],     ah[mf], bl[0], bl[2]);
                    mma_bf16(acc[mf][2 * bq + 1], ah[mf], bl[1], bl[3]);
                    mma_bf16(acc[mf][2 * bq],     al[mf], bh[0], bh[2]);
                    mma_bf16(acc[mf][2 * bq + 1], al[mf], bh[1], bh[3]);
                }
            }
        }
    }

    // epilogue: column max over the 128 rows of this tile
    __syncthreads();
    float* red = (float*)smem;   // [4][128]
    #pragma unroll
    for (int f = 0; f < 8; f++) {
        float t0 = -1e30f, t1 = -1e30f;
        #pragma unroll
        for (int mf = 0; mf < 2; mf++) {
            t0 = fmaxf(t0, fmaxf(acc[mf][f][0], acc[mf][f][2]));
            t1 = fmaxf(t1, fmaxf(acc[mf][f][1], acc[mf][f][3]));
        }
        #pragma unroll
        for (int off = 4; off < 32; off <<= 1) {
            t0 = fmaxf(t0, __shfl_xor_sync(0xffffffffu, t0, off));
            t1 = fmaxf(t1, __shfl_xor_sync(0xffffffffu, t1, off));
        }
        if (lane < 4) {
            red[wm * 128 + wn * 64 + f * 8 + 2 * lane]     = t0;
            red[wm * 128 + wn * 64 + f * 8 + 2 * lane + 1] = t1;
        }
    }
    __syncthreads();
    if (tid < 128) {
        float m = red[tid];
        #pragma unroll
        for (int q = 1; q < 4; q++) m = fmaxf(m, red[q * 128 + tid]);
        unsigned u = __float_as_uint(m);
        unsigned key = (u & 0x80000000u) ? ~u : (u | 0x80000000u);
        atomicMax(&g_rkeys[n0 + tid], key);
    }
}

// ---------------- head ----------------
__global__ void k_h(const float* __restrict__ sb,
                    const float* __restrict__ w1,
                    const float* __restrict__ b1) {
    __shared__ float rs[D2];
    int tid = threadIdx.x;
    for (int j = tid; j < D2; j += 256) {
        unsigned key = g_rkeys[j];
        unsigned u = (key & 0x80000000u) ? (key & 0x7FFFFFFFu) : ~key;
        rs[j] = __uint_as_float(u) + sb[j];
    }
    __syncthreads();
    int g = tid >> 4, s = tid & 15;
    int o = blockIdx.x * 16 + g;
    float accv = 0.f;
    for (int j = s; j < D2; j += 16) accv += w1[o * D2 + j] * rs[j];
    #pragma unroll
    for (int off = 8; off; off >>= 1) accv += __shfl_down_sync(0xffffffffu, accv, off, 16);
    if (s == 0) g_h[o] = tanhf(accv + b1[o]);
}

__global__ void k_out(const float* __restrict__ w2,
                      const float* __restrict__ b2,
                      float* __restrict__ out) {
    int j = threadIdx.x >> 5, lane = threadIdx.x & 31;
    float accv = 0.f;
    for (int l = lane; l < D4; l += 32) accv += g_h[l] * w2[j * D4 + l];
    #pragma unroll
    for (int off = 16; off; off >>= 1) accv += __shfl_down_sync(0xffffffffu, accv, off);
    if (lane == 0) out[j] = accv + b2[j];
}

extern "C" void kernel_launch(void* const* d_in, const int* in_sizes, int n_in,
                              void* d_out, int out_size) {
    const int*   words       = (const int*)d_in[0];
    const int*   wic         = (const int*)d_in[1];
    const float* word_emb    = (const float*)d_in[2];
    const float* chr_emb     = (const float*)d_in[3];
    const float* conv_chr_w  = (const float*)d_in[4];
    const float* conv_chr_b  = (const float*)d_in[5];
    const float* conv_sent_w = (const float*)d_in[6];
    const float* conv_sent_b = (const float*)d_in[7];
    const float* w1          = (const float*)d_in[8];
    const float* b1          = (const float*)d_in[9];
    const float* w2          = (const float*)d_in[10];
    const float* b2          = (const float*)d_in[11];
    float* out = (float*)d_out;

    cudaFuncSetAttribute(k_gemm_mma, cudaFuncAttributeMaxDynamicSharedMemorySize, SMEM_DYN);

    k_tr_wc<<<768, 256>>>(conv_chr_w);
    k_prep_B<<<512, 256>>>(conv_sent_w);
    k_tables<<<64, 256>>>(chr_emb);
    k_build_u<<<W_WORDS, 128>>>(words, wic, word_emb, conv_chr_b);
    dim3 g3(D2 / GN, W_WORDS / GM);     // 4 x 32 = 128 CTAs
    k_gemm_mma<<<g3, 256, SMEM_DYN>>>();
    k_h<<<64, 256>>>(conv_sent_b, w1, b1);
    k_out<<<1, 64>>>(w2, b2, out);
}